// round 16
// baseline (speedup 1.0000x reference)
#include <cuda_runtime.h>
#include <cuda_bf16.h>
#include <math.h>
#include <stdint.h>

#define BATCH 8
#define CDIM 384
#define NHEAD 8
#define CH 48
#define HW 16384
#define EPS 1e-12f

// ---------------- warp-MMA + cp.async helpers (plain sm_80+ PTX) ----------------
__device__ __forceinline__ uint32_t smem_u32(const void* p) {
    uint32_t a;
    asm("{ .reg .u64 t; cvta.to.shared.u64 t, %1; cvt.u32.u64 %0, t; }" : "=r"(a) : "l"(p));
    return a;
}
__device__ __forceinline__ void ldm_x4(uint32_t* r, uint32_t addr) {
    asm volatile("ldmatrix.sync.aligned.m8n8.x4.shared.b16 {%0,%1,%2,%3}, [%4];"
                 : "=r"(r[0]), "=r"(r[1]), "=r"(r[2]), "=r"(r[3]) : "r"(addr));
}
__device__ __forceinline__ void ldm_x4_trans(uint32_t* r, uint32_t addr) {
    asm volatile("ldmatrix.sync.aligned.m8n8.x4.trans.shared.b16 {%0,%1,%2,%3}, [%4];"
                 : "=r"(r[0]), "=r"(r[1]), "=r"(r[2]), "=r"(r[3]) : "r"(addr));
}
__device__ __forceinline__ void mma_bf16(float* d, const uint32_t* a, const uint32_t* b) {
    asm volatile(
        "mma.sync.aligned.m16n8k16.row.col.f32.bf16.bf16.f32 "
        "{%0,%1,%2,%3}, {%4,%5,%6,%7}, {%8,%9}, {%0,%1,%2,%3};"
        : "+f"(d[0]), "+f"(d[1]), "+f"(d[2]), "+f"(d[3])
        : "r"(a[0]), "r"(a[1]), "r"(a[2]), "r"(a[3]), "r"(b[0]), "r"(b[1]));
}
__device__ __forceinline__ void cp_async16(uint32_t saddr, const void* gptr) {
    asm volatile("cp.async.cg.shared.global [%0], [%1], 16;" :: "r"(saddr), "l"(gptr));
}
#define CP_COMMIT() asm volatile("cp.async.commit_group;")
#define CP_WAIT0()  asm volatile("cp.async.wait_group 0;")

// ---------------- scratch ----------------
__device__ float g_G [(size_t)BATCH * CDIM * CDIM];
__device__ float g_Rq[(size_t)BATCH * CDIM * CDIM];
__device__ float g_Rk[(size_t)BATCH * CDIM * CDIM];
__device__ float g_invq[BATCH * CDIM];
__device__ float g_invk[BATCH * CDIM];
__device__ float g_S [BATCH * NHEAD * CH * CH];
__device__ float g_A [BATCH * NHEAD * CH * CH];

__device__ __nv_bfloat16 g_xhi [(size_t)BATCH * CDIM * HW];   // [b][c][n]
__device__ __nv_bfloat16 g_xlo [(size_t)BATCH * CDIM * HW];
__device__ __nv_bfloat16 g_Ghi [(size_t)BATCH * CDIM * CDIM];
__device__ __nv_bfloat16 g_Glo [(size_t)BATCH * CDIM * CDIM];
__device__ __nv_bfloat16 g_BsThi[(size_t)BATCH * CDIM * CDIM]; // [b][m][c]
__device__ __nv_bfloat16 g_BsTlo[(size_t)BATCH * CDIM * CDIM];
__device__ __nv_bfloat16 g_Mhi [(size_t)BATCH * CDIM * CDIM];
__device__ __nv_bfloat16 g_Mlo [(size_t)BATCH * CDIM * CDIM];
__device__ __nv_bfloat16 g_Whi [3 * CDIM * CDIM];
__device__ __nv_bfloat16 g_Wlo [3 * CDIM * CDIM];

// ---------------- converts ----------------
__global__ void convert_plain(const float* __restrict__ x) {
    size_t i = ((size_t)blockIdx.x * 256 + threadIdx.x) * 8;
    float4 v0 = *(const float4*)(x + i);
    float4 v1 = *(const float4*)(x + i + 4);
    float v[8] = {v0.x, v0.y, v0.z, v0.w, v1.x, v1.y, v1.z, v1.w};
    __align__(16) __nv_bfloat16 hh[8], ll[8];
#pragma unroll
    for (int j = 0; j < 8; ++j) {
        __nv_bfloat16 h = __float2bfloat16(v[j]);
        hh[j] = h;
        ll[j] = __float2bfloat16(v[j] - __bfloat162float(h));
    }
    *(uint4*)(g_xhi + i) = *(const uint4*)hh;
    *(uint4*)(g_xlo + i) = *(const uint4*)ll;
}

__global__ void convert_W(const float* __restrict__ wq, const float* __restrict__ wk,
                          const float* __restrict__ wo) {
    int i = blockIdx.x * 256 + threadIdx.x;
    if (i >= CDIM * CDIM) return;
    const float* srcs[3] = {wq, wk, wo};
#pragma unroll
    for (int m = 0; m < 3; ++m) {
        float v = srcs[m][i];
        __nv_bfloat16 h = __float2bfloat16(v);
        g_Whi[m * CDIM * CDIM + i] = h;
        g_Wlo[m * CDIM * CDIM + i] = __float2bfloat16(v - __bfloat162float(h));
    }
}

__global__ void zero_G_kernel() {
    size_t i = (size_t)blockIdx.x * 256 + threadIdx.x;
    if (i < (size_t)BATCH * CDIM * CDIM) g_G[i] = 0.f;
}

__global__ void mirror_convert_G() {
    size_t i = (size_t)blockIdx.x * 256 + threadIdx.x;
    if (i >= (size_t)BATCH * CDIM * CDIM) return;
    size_t bb = i / (CDIM * CDIM);
    int rc = (int)(i % (CDIM * CDIM));
    int r = rc / CDIM, c = rc % CDIM;
    float v;
    if ((r >> 7) > (c >> 7)) {
        v = g_G[bb * CDIM * CDIM + (size_t)c * CDIM + r];
        g_G[i] = v;
    } else {
        v = g_G[i];
    }
    __nv_bfloat16 h = __float2bfloat16(v);
    g_Ghi[i] = h;
    g_Glo[i] = __float2bfloat16(v - __bfloat162float(h));
}

// ---------------- syrk: k16 tiles, 48KB smem -> 4 CTAs/SM ----------------
#define S16_ROWB 48                 // 16 data bf16 (32B) + 8 pad bf16
#define S16_TILE (128 * S16_ROWB)   // 6144
#define S16_AH 0
#define S16_AL (1 * S16_TILE)
#define S16_BH (2 * S16_TILE)
#define S16_BL (3 * S16_TILE)
#define S16_STAGE (4 * S16_TILE)    // 24576
#define S16_SMEM (2 * S16_STAGE)    // 49152

__device__ __forceinline__ void s16_issue(uint32_t sdst,
    const __nv_bfloat16* Ah, const __nv_bfloat16* Al,
    const __nv_bfloat16* Bh, const __nv_bfloat16* Bl,
    int k0, int tid, bool loadB)
{
    int r = tid >> 1, g = tid & 1;
    uint32_t so = (uint32_t)(r * S16_ROWB + g * 16);
    size_t go = (size_t)r * HW + k0 + g * 8;
    cp_async16(sdst + S16_AH + so, Ah + go);
    cp_async16(sdst + S16_AL + so, Al + go);
    if (loadB) {
        cp_async16(sdst + S16_BH + so, Bh + go);
        cp_async16(sdst + S16_BL + so, Bl + go);
    }
}

__device__ __forceinline__ void s16_mma(uint32_t sbase, int lane, int wm, int wn,
                                        float acc[4][4][4],
                                        uint32_t offB_h, uint32_t offB_l) {
    uint32_t a_hi[4][4], a_lo[4][4], b_hi[2][4], b_lo[2][4];
    const uint32_t arow = (uint32_t)(wm * 64 + (lane & 15));
    const uint32_t acol = (lane >> 4) * 16;
#pragma unroll
    for (int mi = 0; mi < 4; ++mi) {
        uint32_t off = (arow + mi * 16) * S16_ROWB + acol;
        ldm_x4(a_hi[mi], sbase + S16_AH + off);
        ldm_x4(a_lo[mi], sbase + S16_AL + off);
    }
    const uint32_t brow = (uint32_t)(wn * 32 + ((lane >> 4) << 3) + (lane & 7));
    const uint32_t bcol = ((lane >> 3) & 1) * 16;
#pragma unroll
    for (int nj = 0; nj < 2; ++nj) {
        uint32_t off = (brow + nj * 16) * S16_ROWB + bcol;
        ldm_x4(b_hi[nj], sbase + offB_h + off);
        ldm_x4(b_lo[nj], sbase + offB_l + off);
    }
#pragma unroll
    for (int t = 0; t < 3; ++t) {
        const uint32_t (*ap)[4] = (t == 2) ? a_lo : a_hi;
        const uint32_t (*bp)[4] = (t == 1) ? b_lo : b_hi;
#pragma unroll
        for (int mi = 0; mi < 4; ++mi)
#pragma unroll
            for (int nj = 0; nj < 2; ++nj) {
                mma_bf16(acc[mi][nj * 2 + 0], ap[mi], &bp[nj][0]);
                mma_bf16(acc[mi][nj * 2 + 1], ap[mi], &bp[nj][2]);
            }
    }
}

__global__ __launch_bounds__(256) void syrk_mma() {
    extern __shared__ __align__(16) char sm[];
    const int tid = threadIdx.x, lane = tid & 31, wid = tid >> 5;
    const int wm = wid & 1, wn = wid >> 1;
    const int TI[6] = {0, 0, 0, 1, 1, 2};
    const int TJ[6] = {0, 1, 2, 1, 2, 2};
    const int ti = TI[blockIdx.x], tj = TJ[blockIdx.x];
    const bool diag = (ti == tj);
    const int b = blockIdx.z;
    const int kb = blockIdx.y * 1024;

    const __nv_bfloat16* Ah = g_xhi + ((size_t)(b * CDIM + ti * 128)) * HW;
    const __nv_bfloat16* Al = g_xlo + ((size_t)(b * CDIM + ti * 128)) * HW;
    const __nv_bfloat16* Bh = g_xhi + ((size_t)(b * CDIM + tj * 128)) * HW;
    const __nv_bfloat16* Bl = g_xlo + ((size_t)(b * CDIM + tj * 128)) * HW;

    const uint32_t offB_h = diag ? S16_AH : S16_BH;
    const uint32_t offB_l = diag ? S16_AL : S16_BL;

    float acc[4][4][4];
#pragma unroll
    for (int i = 0; i < 4; ++i)
#pragma unroll
        for (int j = 0; j < 4; ++j)
#pragma unroll
            for (int k = 0; k < 4; ++k) acc[i][j][k] = 0.f;

    const uint32_t sb = smem_u32(sm);
    s16_issue(sb, Ah, Al, Bh, Bl, kb, tid, !diag);
    CP_COMMIT();

    const int NCH = 64;   // 1024 k per CTA, 16 per chunk
    for (int ch = 0; ch < NCH; ++ch) {
        CP_WAIT0();
        __syncthreads();
        if (ch < NCH - 1) {
            s16_issue(sb + ((ch + 1) & 1) * S16_STAGE, Ah, Al, Bh, Bl,
                      kb + (ch + 1) * 16, tid, !diag);
            CP_COMMIT();
        }
        s16_mma(sb + (ch & 1) * S16_STAGE, lane, wm, wn, acc, offB_h, offB_l);
    }

    float* Gp = g_G + (size_t)b * CDIM * CDIM;
    const int r0 = ti * 128 + wm * 64;
    const int c0 = tj * 128 + wn * 32;
#pragma unroll
    for (int mi = 0; mi < 4; ++mi)
#pragma unroll
        for (int f = 0; f < 4; ++f) {
            int row = r0 + mi * 16 + (lane >> 2);
            int col = c0 + f * 8 + (lane & 3) * 2;
            atomicAdd(&Gp[(size_t)row * CDIM + col],           acc[mi][f][0]);
            atomicAdd(&Gp[(size_t)row * CDIM + col + 1],       acc[mi][f][1]);
            atomicAdd(&Gp[(size_t)(row + 8) * CDIM + col],     acc[mi][f][2]);
            atomicAdd(&Gp[(size_t)(row + 8) * CDIM + col + 1], acc[mi][f][3]);
        }
}

// ---------------- k32 geometry for wgemm/out (R13 proven) ----------------
#define ROWB 80
#define TILE_BYTES (128 * ROWB)
#define OFF_AH 0
#define OFF_AL (1 * TILE_BYTES)
#define OFF_BH (2 * TILE_BYTES)
#define OFF_BL (3 * TILE_BYTES)
#define STAGE_BYTES (4 * TILE_BYTES)   // 40960
#define PIPE_SMEM (2 * STAGE_BYTES)    // 81920

__device__ __forceinline__ void issue_stage(uint32_t sdst,
    const __nv_bfloat16* Ah, const __nv_bfloat16* Al,
    const __nv_bfloat16* Bh, const __nv_bfloat16* Bl,
    size_t strideA, size_t strideB, int k0, int tid)
{
#pragma unroll
    for (int t = 0; t < 2; ++t) {
        int idx = t * 256 + tid;
        int r = idx >> 2, g = idx & 3;
        uint32_t so = (uint32_t)(r * ROWB + g * 16);
        size_t goA = (size_t)r * strideA + k0 + g * 8;
        size_t goB = (size_t)r * strideB + k0 + g * 8;
        cp_async16(sdst + OFF_AH + so, Ah + goA);
        cp_async16(sdst + OFF_AL + so, Al + goA);
        cp_async16(sdst + OFF_BH + so, Bh + goB);
        cp_async16(sdst + OFF_BL + so, Bl + goB);
    }
}

__device__ __forceinline__ void mma_chunk(uint32_t sbase, int lane, int wm, int wn,
                                          float acc[4][4][4]) {
#pragma unroll
    for (int kk = 0; kk < 2; ++kk) {
        uint32_t a_hi[4][4], a_lo[4][4], b_hi[2][4], b_lo[2][4];
        const uint32_t arow = (uint32_t)(wm * 64 + (lane & 15));
        const uint32_t acol = ((lane >> 4) * 16) + kk * 32;
#pragma unroll
        for (int mi = 0; mi < 4; ++mi) {
            uint32_t off = (arow + mi * 16) * ROWB + acol;
            ldm_x4(a_hi[mi], sbase + OFF_AH + off);
            ldm_x4(a_lo[mi], sbase + OFF_AL + off);
        }
        const uint32_t brow = (uint32_t)(wn * 32 + ((lane >> 4) << 3) + (lane & 7));
        const uint32_t bcol = (((lane >> 3) & 1) * 16) + kk * 32;
#pragma unroll
        for (int nj = 0; nj < 2; ++nj) {
            uint32_t off = (brow + nj * 16) * ROWB + bcol;
            ldm_x4(b_hi[nj], sbase + OFF_BH + off);
            ldm_x4(b_lo[nj], sbase + OFF_BL + off);
        }
#pragma unroll
        for (int t = 0; t < 3; ++t) {
            const uint32_t (*ap)[4] = (t == 2) ? a_lo : a_hi;
            const uint32_t (*bp)[4] = (t == 1) ? b_lo : b_hi;
#pragma unroll
            for (int mi = 0; mi < 4; ++mi)
#pragma unroll
                for (int nj = 0; nj < 2; ++nj) {
                    mma_bf16(acc[mi][nj * 2 + 0], ap[mi], &bp[nj][0]);
                    mma_bf16(acc[mi][nj * 2 + 1], ap[mi], &bp[nj][2]);
                }
        }
    }
}

__global__ __launch_bounds__(256) void wgemm_mma(int mode) {
    extern __shared__ __align__(16) char sm[];
    const int tid = threadIdx.x, lane = tid & 31, wid = tid >> 5;
    const int wm = wid & 1, wn = wid >> 1;
    const int o0 = (blockIdx.x % 3) * 128;
    const int j0 = (blockIdx.x / 3) * 128;
    const int b = blockIdx.y;
    const int which = blockIdx.z;
    const size_t CC = (size_t)CDIM * CDIM;

    const int widx = mode ? 2 : which;
    const __nv_bfloat16* Ah = g_Whi + (size_t)widx * CC + (size_t)o0 * CDIM;
    const __nv_bfloat16* Al = g_Wlo + (size_t)widx * CC + (size_t)o0 * CDIM;
    const __nv_bfloat16* Bh = (mode ? g_BsThi : g_Ghi) + (size_t)b * CC + (size_t)j0 * CDIM;
    const __nv_bfloat16* Bl = (mode ? g_BsTlo : g_Glo) + (size_t)b * CC + (size_t)j0 * CDIM;

    float acc[4][4][4];
#pragma unroll
    for (int i = 0; i < 4; ++i)
#pragma unroll
        for (int j = 0; j < 4; ++j)
#pragma unroll
            for (int k = 0; k < 4; ++k) acc[i][j][k] = 0.f;

    const uint32_t sb = smem_u32(sm);
    issue_stage(sb, Ah, Al, Bh, Bl, CDIM, CDIM, 0, tid);
    CP_COMMIT();

    for (int ch = 0; ch < 12; ++ch) {
        CP_WAIT0();
        __syncthreads();
        if (ch < 11) {
            issue_stage(sb + ((ch + 1) & 1) * STAGE_BYTES, Ah, Al, Bh, Bl,
                        CDIM, CDIM, (ch + 1) * 32, tid);
            CP_COMMIT();
        }
        mma_chunk(sb + (ch & 1) * STAGE_BYTES, lane, wm, wn, acc);
    }

    if (mode == 0) {
        float* C = (which ? g_Rk : g_Rq) + b * CC;
#pragma unroll
        for (int mi = 0; mi < 4; ++mi)
#pragma unroll
            for (int f = 0; f < 4; ++f) {
                int o = o0 + wm * 64 + mi * 16 + (lane >> 2);
                int j = j0 + wn * 32 + f * 8 + (lane & 3) * 2;
                *(float2*)&C[(size_t)o * CDIM + j] =
                    make_float2(acc[mi][f][0], acc[mi][f][1]);
                *(float2*)&C[(size_t)(o + 8) * CDIM + j] =
                    make_float2(acc[mi][f][2], acc[mi][f][3]);
            }
    } else {
#pragma unroll
        for (int mi = 0; mi < 4; ++mi)
#pragma unroll
            for (int f = 0; f < 4; ++f) {
                int o = o0 + wm * 64 + mi * 16 + (lane >> 2);
                int j = j0 + wn * 32 + f * 8 + (lane & 3) * 2;
#pragma unroll
                for (int half = 0; half < 2; ++half) {
                    float v0 = acc[mi][f][half * 2 + 0];
                    float v1 = acc[mi][f][half * 2 + 1];
                    __nv_bfloat16 h0 = __float2bfloat16(v0);
                    __nv_bfloat16 h1 = __float2bfloat16(v1);
                    __nv_bfloat16 l0 = __float2bfloat16(v0 - __bfloat162float(h0));
                    __nv_bfloat16 l1 = __float2bfloat16(v1 - __bfloat162float(h1));
                    size_t off = b * CC + (size_t)(o + half * 8) * CDIM + j;
                    *(__nv_bfloat162*)(g_Mhi + off) = __nv_bfloat162(h0, h1);
                    *(__nv_bfloat162*)(g_Mlo + off) = __nv_bfloat162(l0, l1);
                }
            }
    }
}

// ---------------- out = M @ x: B via ldmatrix.trans from plain x (2-stage) ----------------
#define O_BROWB 272
#define O_AH 0
#define O_AL 10240
#define O_BH 20480
#define O_BL (20480 + 32 * O_BROWB)     // 29184
#define O_STAGE (O_BL + 32 * O_BROWB)   // 37888
#define OUT_SMEM (2 * O_STAGE)          // 75776

__global__ __launch_bounds__(256) void out_mma(float* __restrict__ out) {
    extern __shared__ __align__(16) char sm[];
    const int tid = threadIdx.x, lane = tid & 31, wid = tid >> 5;
    const int wm = wid & 1, wn = wid >> 1;
    const int ntile = blockIdx.x;
    const int otile = blockIdx.y;
    const int b = blockIdx.z;
    const size_t CC = (size_t)CDIM * CDIM;

    const __nv_bfloat16* Ah = g_Mhi + (size_t)b * CC + (size_t)(otile * 128) * CDIM;
    const __nv_bfloat16* Al = g_Mlo + (size_t)b * CC + (size_t)(otile * 128) * CDIM;
    const __nv_bfloat16* Xh = g_xhi + (size_t)b * CDIM * HW + (size_t)ntile * 128;
    const __nv_bfloat16* Xl = g_xlo + (size_t)b * CDIM * HW + (size_t)ntile * 128;

    float acc[4][4][4];
#pragma unroll
    for (int i = 0; i < 4; ++i)
#pragma unroll
        for (int j = 0; j < 4; ++j)
#pragma unroll
            for (int k = 0; k < 4; ++k) acc[i][j][k] = 0.f;

    const uint32_t sb = smem_u32(sm);

    auto issue = [&](uint32_t sdst, int cbase) {
#pragma unroll
        for (int t = 0; t < 2; ++t) {
            int idx = t * 256 + tid;
            {   // A: M tile 128o x 32c
                int r = idx >> 2, g = idx & 3;
                uint32_t so = (uint32_t)(r * ROWB + g * 16);
                size_t go = (size_t)r * CDIM + cbase + g * 8;
                cp_async16(sdst + O_AH + so, Ah + go);
                cp_async16(sdst + O_AL + so, Al + go);
            }
            {   // B: x tile 32c x 128n
                int r = idx >> 4, c16 = idx & 15;
                uint32_t so = (uint32_t)(r * O_BROWB + c16 * 16);
                size_t go = (size_t)(cbase + r) * HW + c16 * 8;
                cp_async16(sdst + O_BH + so, Xh + go);
                cp_async16(sdst + O_BL + so, Xl + go);
            }
        }
    };

    issue(sb, 0);
    CP_COMMIT();

    for (int ch = 0; ch < 12; ++ch) {
        CP_WAIT0();
        __syncthreads();
        if (ch < 11) {
            issue(sb + ((ch + 1) & 1) * O_STAGE, (ch + 1) * 32);
            CP_COMMIT();
        }
        const uint32_t sbase = sb + (ch & 1) * O_STAGE;
#pragma unroll
        for (int kk = 0; kk < 2; ++kk) {
            uint32_t a_hi[4][4], a_lo[4][4], b_hi[2][4], b_lo[2][4];
            const uint32_t arow = (uint32_t)(wm * 64 + (lane & 15));
            const uint32_t acol = ((lane >> 4) * 16) + kk * 32;
#pragma unroll
            for (int mi = 0; mi < 4; ++mi) {
                uint32_t off = (arow + mi * 16) * ROWB + acol;
                ldm_x4(a_hi[mi], sbase + O_AH + off);
                ldm_x4(a_lo[mi], sbase + O_AL + off);
            }
            const uint32_t brow = (uint32_t)(kk * 16 + (lane & 7) + ((lane >> 3) & 1) * 8);
#pragma unroll
            for (int nj = 0; nj < 2; ++nj) {
                uint32_t bcol = (uint32_t)(wn * 32 + nj * 16 + (lane >> 4) * 8) * 2;
                uint32_t off = brow * O_BROWB + bcol;
                ldm_x4_trans(b_hi[nj], sbase + O_BH + off);
                ldm_x4_trans(b_lo[nj], sbase + O_BL + off);
            }
#pragma unroll
            for (int t = 0; t < 3; ++t) {
                const uint32_t (*ap)[4] = (t == 2) ? a_lo : a_hi;
                const uint32_t (*bp)[4] = (t == 1) ? b_lo : b_hi;
#pragma unroll
                for (int mi = 0; mi < 4; ++mi)
#pragma unroll
                    for (int nj = 0; nj < 2; ++nj) {
                        mma_bf16(acc[mi][nj * 2 + 0], ap[mi], &bp[nj][0]);
                        mma_bf16(acc[mi][nj * 2 + 1], ap[mi], &bp[nj][2]);
                    }
            }
        }
    }

    const int o0 = otile * 128 + wm * 64;
    const int n0 = ntile * 128 + wn * 32;
#pragma unroll
    for (int mi = 0; mi < 4; ++mi)
#pragma unroll
        for (int f = 0; f < 4; ++f) {
            int o = o0 + mi * 16 + (lane >> 2);
            int n = n0 + f * 8 + (lane & 3) * 2;
            *(float2*)&out[((size_t)b * CDIM + o) * HW + n] =
                make_float2(acc[mi][f][0], acc[mi][f][1]);
            *(float2*)&out[((size_t)b * CDIM + o + 8) * HW + n] =
                make_float2(acc[mi][f][2], acc[mi][f][3]);
        }
}

// ---------------- fp32 SIMT tail ----------------
__global__ void norms_kernel(const float* __restrict__ wq, const float* __restrict__ wk) {
    const int which = blockIdx.x;
    const int b = blockIdx.y;
    const float* R = (which ? g_Rk : g_Rq) + (size_t)b * CDIM * CDIM;
    const float* W = which ? wk : wq;
    float* inv = (which ? g_invk : g_invq) + b * CDIM;
    const int lane = threadIdx.x & 31;
    const int wd = threadIdx.x >> 5;
    for (int r = wd; r < CDIM; r += 12) {
        float s = 0.f;
        for (int j = lane; j < CDIM; j += 32)
            s = fmaf(R[(size_t)r * CDIM + j], W[(size_t)r * CDIM + j], s);
#pragma unroll
        for (int o = 16; o; o >>= 1) s += __shfl_xor_sync(0xffffffffu, s, o);
        if (lane == 0) inv[r] = 1.f / fmaxf(sqrtf(fmaxf(s, 0.f)), EPS);
    }
}

__global__ __launch_bounds__(256) void s_kernel(const float* __restrict__ wk) {
    const int bh = blockIdx.x;
    const int b = bh >> 3;
    const int h = bh & 7;
    const int tid = threadIdx.x;

    __shared__ float qs[CH][68];
    __shared__ float ks[CH][68];

    const int c0 = (tid >> 4) * 3;
    const int d0 = (tid & 15) * 3;

    float acc[3][3];
#pragma unroll
    for (int i = 0; i < 3; ++i)
#pragma unroll
        for (int j = 0; j < 3; ++j) acc[i][j] = 0.f;

    const float* Rq = g_Rq + (size_t)b * CDIM * CDIM + (size_t)(h * CH) * CDIM;
    const float* Wk = wk + (size_t)(h * CH) * CDIM;

    for (int ck = 0; ck < 6; ++ck) {
        const int koff = ck * 64;
#pragma unroll
        for (int t = 0; t < 3; ++t) {
            int idx = t * 256 + tid;
            int row = idx >> 4;
            int col = (idx & 15) * 4;
            *(float4*)&qs[row][col] = *(const float4*)(Rq + (size_t)row * CDIM + koff + col);
            *(float4*)&ks[row][col] = *(const float4*)(Wk + (size_t)row * CDIM + koff + col);
        }
        __syncthreads();
#pragma unroll 8
        for (int kk = 0; kk < 64; ++kk) {
            float q0 = qs[c0 + 0][kk], q1 = qs[c0 + 1][kk], q2 = qs[c0 + 2][kk];
            float k0 = ks[d0 + 0][kk], k1 = ks[d0 + 1][kk], k2 = ks[d0 + 2][kk];
            acc[0][0] = fmaf(q0, k0, acc[0][0]);
            acc[0][1] = fmaf(q0, k1, acc[0][1]);
            acc[0][2] = fmaf(q0, k2, acc[0][2]);
            acc[1][0] = fmaf(q1, k0, acc[1][0]);
            acc[1][1] = fmaf(q1, k1, acc[1][1]);
            acc[1][2] = fmaf(q1, k2, acc[1][2]);
            acc[2][0] = fmaf(q2, k0, acc[2][0]);
            acc[2][1] = fmaf(q2, k1, acc[2][1]);
            acc[2][2] = fmaf(q2, k2, acc[2][2]);
        }
        __syncthreads();
    }

    float* Sb = g_S + (size_t)bh * CH * CH;
#pragma unroll
    for (int i = 0; i < 3; ++i)
#pragma unroll
        for (int j = 0; j < 3; ++j)
            Sb[(c0 + i) * CH + (d0 + j)] = acc[i][j];
}

__global__ void attn_softmax_kernel(const float* __restrict__ temperature) {
    const int bh = blockIdx.x;
    const int b = bh >> 3;
    const int h = bh & 7;
    const int c = threadIdx.x;
    if (c >= CH) return;

    const float t = temperature[h];
    const float sq = g_invq[b * CDIM + h * CH + c] * t;
    const float* Srow = g_S + (size_t)bh * CH * CH + c * CH;
    const float* ik = g_invk + b * CDIM + h * CH;

    float v[CH];
    float m = -1e30f;
#pragma unroll
    for (int d = 0; d < CH; ++d) {
        v[d] = Srow[d] * sq * ik[d];
        m = fmaxf(m, v[d]);
    }
    float sum = 0.f;
#pragma unroll
    for (int d = 0; d < CH; ++d) {
        v[d] = __expf(v[d] - m);
        sum += v[d];
    }
    float inv = 1.f / sum;
    float* Arow = g_A + (size_t)bh * CH * CH + c * CH;
#pragma unroll
    for (int d = 0; d < CH; ++d) Arow[d] = v[d] * inv;
}

__global__ __launch_bounds__(384) void bstack_T(const float* __restrict__ wv) {
    const int bh = blockIdx.x;
    const int b = bh >> 3;
    const int h = bh & 7;

    __shared__ float As[CH * CH];
    const float* Ahp = g_A + (size_t)bh * CH * CH;
    for (int i = threadIdx.x; i < CH * CH; i += 384) As[i] = Ahp[i];
    __syncthreads();

    const int m = threadIdx.x;
    float acc[CH];
#pragma unroll
    for (int i = 0; i < CH; ++i) acc[i] = 0.f;

    const float* wvp = wv + (size_t)(h * CH) * CDIM + m;
    for (int d = 0; d < CH; ++d) {
        float wvv = wvp[(size_t)d * CDIM];
#pragma unroll
        for (int cp = 0; cp < CH; ++cp) acc[cp] = fmaf(As[cp * CH + d], wvv, acc[cp]);
    }
    size_t base = ((size_t)b * CDIM + m) * CDIM + h * CH;
    __align__(16) __nv_bfloat16 hh[CH], ll[CH];
#pragma unroll
    for (int cp = 0; cp < CH; ++cp) {
        __nv_bfloat16 hv = __float2bfloat16(acc[cp]);
        hh[cp] = hv;
        ll[cp] = __float2bfloat16(acc[cp] - __bfloat162float(hv));
    }
#pragma unroll
    for (int q = 0; q < CH / 4; ++q) {
        *(uint2*)(g_BsThi + base + q * 4) = *(const uint2*)(hh + q * 4);
        *(uint2*)(g_BsTlo + base + q * 4) = *(const uint2*)(ll + q * 4);
    }
}

// ---------------- launcher ----------------
extern "C" void kernel_launch(void* const* d_in, const int* in_sizes, int n_in,
                              void* d_out, int out_size) {
    const float* x    = (const float*)d_in[0];
    const float* wq   = (const float*)d_in[1];
    const float* wk   = (const float*)d_in[2];
    const float* wv   = (const float*)d_in[3];
    const float* wo   = (const float*)d_in[4];
    const float* temp = (const float*)d_in[5];
    float* out = (float*)d_out;

    cudaFuncSetAttribute(syrk_mma, cudaFuncAttributeMaxDynamicSharedMemorySize, S16_SMEM);
    cudaFuncSetAttribute(wgemm_mma, cudaFuncAttributeMaxDynamicSharedMemorySize, PIPE_SMEM);
    cudaFuncSetAttribute(out_mma, cudaFuncAttributeMaxDynamicSharedMemorySize, OUT_SMEM);

    const size_t CC = (size_t)CDIM * CDIM;
    const int nG = (int)(((size_t)BATCH * CC + 255) / 256);

    convert_plain<<<24576, 256>>>(x);
    convert_W<<<(CDIM * CDIM + 255) / 256, 256>>>(wq, wk, wo);
    zero_G_kernel<<<nG, 256>>>();
    syrk_mma<<<dim3(6, 16, BATCH), 256, S16_SMEM>>>();
    mirror_convert_G<<<nG, 256>>>();

    wgemm_mma<<<dim3(9, BATCH, 2), 256, PIPE_SMEM>>>(0);   // Rq, Rk

    norms_kernel<<<dim3(2, BATCH), 384>>>(wq, wk);
    s_kernel<<<BATCH * NHEAD, 256>>>(wk);
    attn_softmax_kernel<<<BATCH * NHEAD, 64>>>(temp);
    bstack_T<<<BATCH * NHEAD, 384>>>(wv);

    wgemm_mma<<<dim3(9, BATCH, 1), 256, PIPE_SMEM>>>(1);   // Mhi/Mlo

    out_mma<<<dim3(HW / 128, 3, BATCH), 256, OUT_SMEM>>>(out);
}

// round 17
// speedup vs baseline: 1.1130x; 1.1130x over previous
#include <cuda_runtime.h>
#include <cuda_bf16.h>
#include <math.h>
#include <stdint.h>

#define BATCH 8
#define CDIM 384
#define NHEAD 8
#define CH 48
#define HW 16384
#define EPS 1e-12f

// ---------------- warp-MMA + cp.async helpers (plain sm_80+ PTX) ----------------
__device__ __forceinline__ uint32_t smem_u32(const void* p) {
    uint32_t a;
    asm("{ .reg .u64 t; cvta.to.shared.u64 t, %1; cvt.u32.u64 %0, t; }" : "=r"(a) : "l"(p));
    return a;
}
__device__ __forceinline__ void ldm_x4(uint32_t* r, uint32_t addr) {
    asm volatile("ldmatrix.sync.aligned.m8n8.x4.shared.b16 {%0,%1,%2,%3}, [%4];"
                 : "=r"(r[0]), "=r"(r[1]), "=r"(r[2]), "=r"(r[3]) : "r"(addr));
}
__device__ __forceinline__ void ldm_x4_trans(uint32_t* r, uint32_t addr) {
    asm volatile("ldmatrix.sync.aligned.m8n8.x4.trans.shared.b16 {%0,%1,%2,%3}, [%4];"
                 : "=r"(r[0]), "=r"(r[1]), "=r"(r[2]), "=r"(r[3]) : "r"(addr));
}
__device__ __forceinline__ void mma_bf16(float* d, const uint32_t* a, const uint32_t* b) {
    asm volatile(
        "mma.sync.aligned.m16n8k16.row.col.f32.bf16.bf16.f32 "
        "{%0,%1,%2,%3}, {%4,%5,%6,%7}, {%8,%9}, {%0,%1,%2,%3};"
        : "+f"(d[0]), "+f"(d[1]), "+f"(d[2]), "+f"(d[3])
        : "r"(a[0]), "r"(a[1]), "r"(a[2]), "r"(a[3]), "r"(b[0]), "r"(b[1]));
}
__device__ __forceinline__ void cp_async16(uint32_t saddr, const void* gptr) {
    asm volatile("cp.async.cg.shared.global [%0], [%1], 16;" :: "r"(saddr), "l"(gptr));
}
#define CP_COMMIT() asm volatile("cp.async.commit_group;")
#define CP_WAIT0()  asm volatile("cp.async.wait_group 0;")

// ---------------- scratch ----------------
__device__ float g_G [(size_t)BATCH * CDIM * CDIM];
__device__ float g_Rq[(size_t)BATCH * CDIM * CDIM];
__device__ float g_Rk[(size_t)BATCH * CDIM * CDIM];
__device__ float g_invq[BATCH * CDIM];
__device__ float g_invk[BATCH * CDIM];
__device__ float g_S [BATCH * NHEAD * CH * CH];
__device__ float g_A [BATCH * NHEAD * CH * CH];

__device__ __nv_bfloat16 g_xhi [(size_t)BATCH * CDIM * HW];   // [b][c][n]
__device__ __nv_bfloat16 g_xlo [(size_t)BATCH * CDIM * HW];
__device__ __nv_bfloat16 g_Ghi [(size_t)BATCH * CDIM * CDIM];
__device__ __nv_bfloat16 g_Glo [(size_t)BATCH * CDIM * CDIM];
__device__ __nv_bfloat16 g_BsThi[(size_t)BATCH * CDIM * CDIM]; // [b][m][c]
__device__ __nv_bfloat16 g_BsTlo[(size_t)BATCH * CDIM * CDIM];
__device__ __nv_bfloat16 g_Mhi [(size_t)BATCH * CDIM * CDIM];
__device__ __nv_bfloat16 g_Mlo [(size_t)BATCH * CDIM * CDIM];
__device__ __nv_bfloat16 g_Whi [3 * CDIM * CDIM];
__device__ __nv_bfloat16 g_Wlo [3 * CDIM * CDIM];

// ---------------- converts (zero_G fused into convert_plain) ----------------
__global__ void convert_plain(const float* __restrict__ x) {
    size_t gid = (size_t)blockIdx.x * 256 + threadIdx.x;
    size_t i = gid * 8;
    float4 v0 = *(const float4*)(x + i);
    float4 v1 = *(const float4*)(x + i + 4);
    float v[8] = {v0.x, v0.y, v0.z, v0.w, v1.x, v1.y, v1.z, v1.w};
    __align__(16) __nv_bfloat16 hh[8], ll[8];
#pragma unroll
    for (int j = 0; j < 8; ++j) {
        __nv_bfloat16 h = __float2bfloat16(v[j]);
        hh[j] = h;
        ll[j] = __float2bfloat16(v[j] - __bfloat162float(h));
    }
    *(uint4*)(g_xhi + i) = *(const uint4*)hh;
    *(uint4*)(g_xlo + i) = *(const uint4*)ll;
    // fused: zero the G accumulator (1.18M elems << 6.29M threads)
    if (gid < (size_t)BATCH * CDIM * CDIM) g_G[gid] = 0.f;
}

__global__ void convert_W(const float* __restrict__ wq, const float* __restrict__ wk,
                          const float* __restrict__ wo) {
    int i = blockIdx.x * 256 + threadIdx.x;
    if (i >= CDIM * CDIM) return;
    const float* srcs[3] = {wq, wk, wo};
#pragma unroll
    for (int m = 0; m < 3; ++m) {
        float v = srcs[m][i];
        __nv_bfloat16 h = __float2bfloat16(v);
        g_Whi[m * CDIM * CDIM + i] = h;
        g_Wlo[m * CDIM * CDIM + i] = __float2bfloat16(v - __bfloat162float(h));
    }
}

__global__ void mirror_convert_G() {
    size_t i = (size_t)blockIdx.x * 256 + threadIdx.x;
    if (i >= (size_t)BATCH * CDIM * CDIM) return;
    size_t bb = i / (CDIM * CDIM);
    int rc = (int)(i % (CDIM * CDIM));
    int r = rc / CDIM, c = rc % CDIM;
    float v;
    if ((r >> 7) > (c >> 7)) {
        v = g_G[bb * CDIM * CDIM + (size_t)c * CDIM + r];
        g_G[i] = v;
    } else {
        v = g_G[i];
    }
    __nv_bfloat16 h = __float2bfloat16(v);
    g_Ghi[i] = h;
    g_Glo[i] = __float2bfloat16(v - __bfloat162float(h));
}

// ---------------- MMA tile geometry ----------------
#define ROWB 80
#define TILE_BYTES (128 * ROWB)
#define OFF_AH 0
#define OFF_AL (1 * TILE_BYTES)
#define OFF_BH (2 * TILE_BYTES)
#define OFF_BL (3 * TILE_BYTES)
#define STAGE_BYTES (4 * TILE_BYTES)   // 40960
#define PIPE_SMEM (2 * STAGE_BYTES)    // 81920

__device__ __forceinline__ void issue_stage(uint32_t sdst,
    const __nv_bfloat16* Ah, const __nv_bfloat16* Al,
    const __nv_bfloat16* Bh, const __nv_bfloat16* Bl,
    size_t strideA, size_t strideB, int k0, int tid, bool loadB)
{
#pragma unroll
    for (int t = 0; t < 2; ++t) {
        int idx = t * 256 + tid;
        int r = idx >> 2, g = idx & 3;
        uint32_t so = (uint32_t)(r * ROWB + g * 16);
        size_t goA = (size_t)r * strideA + k0 + g * 8;
        cp_async16(sdst + OFF_AH + so, Ah + goA);
        cp_async16(sdst + OFF_AL + so, Al + goA);
        if (loadB) {
            size_t goB = (size_t)r * strideB + k0 + g * 8;
            cp_async16(sdst + OFF_BH + so, Bh + goB);
            cp_async16(sdst + OFF_BL + so, Bl + goB);
        }
    }
}

__device__ __forceinline__ void mma_chunk(uint32_t sbase, int lane, int wm, int wn,
                                          float acc[4][4][4],
                                          uint32_t offB_h, uint32_t offB_l) {
#pragma unroll
    for (int kk = 0; kk < 2; ++kk) {
        uint32_t a_hi[4][4], a_lo[4][4], b_hi[2][4], b_lo[2][4];
        const uint32_t arow = (uint32_t)(wm * 64 + (lane & 15));
        const uint32_t acol = ((lane >> 4) * 16) + kk * 32;
#pragma unroll
        for (int mi = 0; mi < 4; ++mi) {
            uint32_t off = (arow + mi * 16) * ROWB + acol;
            ldm_x4(a_hi[mi], sbase + OFF_AH + off);
            ldm_x4(a_lo[mi], sbase + OFF_AL + off);
        }
        const uint32_t brow = (uint32_t)(wn * 32 + ((lane >> 4) << 3) + (lane & 7));
        const uint32_t bcol = (((lane >> 3) & 1) * 16) + kk * 32;
#pragma unroll
        for (int nj = 0; nj < 2; ++nj) {
            uint32_t off = (brow + nj * 16) * ROWB + bcol;
            ldm_x4(b_hi[nj], sbase + offB_h + off);
            ldm_x4(b_lo[nj], sbase + offB_l + off);
        }
#pragma unroll
        for (int t = 0; t < 3; ++t) {
            const uint32_t (*ap)[4] = (t == 2) ? a_lo : a_hi;
            const uint32_t (*bp)[4] = (t == 1) ? b_lo : b_hi;
#pragma unroll
            for (int mi = 0; mi < 4; ++mi)
#pragma unroll
                for (int nj = 0; nj < 2; ++nj) {
                    mma_bf16(acc[mi][nj * 2 + 0], ap[mi], &bp[nj][0]);
                    mma_bf16(acc[mi][nj * 2 + 1], ap[mi], &bp[nj][2]);
                }
        }
    }
}

// ---------------- syrk: 12 uneven k-splits for ~2.0-wave schedule ----------------
#define KSPLIT 12
__global__ __launch_bounds__(256) void syrk_mma() {
    extern __shared__ __align__(16) char sm[];
    const int tid = threadIdx.x, lane = tid & 31, wid = tid >> 5;
    const int wm = wid & 1, wn = wid >> 1;
    const int TI[6] = {0, 0, 0, 1, 1, 2};
    const int TJ[6] = {0, 1, 2, 1, 2, 2};
    const int ti = TI[blockIdx.x], tj = TJ[blockIdx.x];
    const bool diag = (ti == tj);
    const int b = blockIdx.z;

    // 512 k32-chunks split over 12 CTAs: first 8 get 43, last 4 get 42.
    const int ks = blockIdx.y;
    const int ch0 = ks * 42 + min(ks, 8);
    const int nch = 42 + (ks < 8 ? 1 : 0);
    const int kb = ch0 * 32;

    const __nv_bfloat16* Ah = g_xhi + ((size_t)(b * CDIM + ti * 128)) * HW;
    const __nv_bfloat16* Al = g_xlo + ((size_t)(b * CDIM + ti * 128)) * HW;
    const __nv_bfloat16* Bh = g_xhi + ((size_t)(b * CDIM + tj * 128)) * HW;
    const __nv_bfloat16* Bl = g_xlo + ((size_t)(b * CDIM + tj * 128)) * HW;

    const uint32_t offB_h = diag ? OFF_AH : OFF_BH;
    const uint32_t offB_l = diag ? OFF_AL : OFF_BL;

    float acc[4][4][4];
#pragma unroll
    for (int i = 0; i < 4; ++i)
#pragma unroll
        for (int j = 0; j < 4; ++j)
#pragma unroll
            for (int k = 0; k < 4; ++k) acc[i][j][k] = 0.f;

    const uint32_t sb = smem_u32(sm);
    issue_stage(sb, Ah, Al, Bh, Bl, HW, HW, kb, tid, !diag);
    CP_COMMIT();

    for (int ch = 0; ch < nch; ++ch) {
        CP_WAIT0();
        __syncthreads();
        if (ch < nch - 1) {
            issue_stage(sb + ((ch + 1) & 1) * STAGE_BYTES, Ah, Al, Bh, Bl,
                        HW, HW, kb + (ch + 1) * 32, tid, !diag);
            CP_COMMIT();
        }
        mma_chunk(sb + (ch & 1) * STAGE_BYTES, lane, wm, wn, acc, offB_h, offB_l);
    }

    float* Gp = g_G + (size_t)b * CDIM * CDIM;
    const int r0 = ti * 128 + wm * 64;
    const int c0 = tj * 128 + wn * 32;
#pragma unroll
    for (int mi = 0; mi < 4; ++mi)
#pragma unroll
        for (int f = 0; f < 4; ++f) {
            int row = r0 + mi * 16 + (lane >> 2);
            int col = c0 + f * 8 + (lane & 3) * 2;
            atomicAdd(&Gp[(size_t)row * CDIM + col],           acc[mi][f][0]);
            atomicAdd(&Gp[(size_t)row * CDIM + col + 1],       acc[mi][f][1]);
            atomicAdd(&Gp[(size_t)(row + 8) * CDIM + col],     acc[mi][f][2]);
            atomicAdd(&Gp[(size_t)(row + 8) * CDIM + col + 1], acc[mi][f][3]);
        }
}

// ---------------- wgemm: C = W-split @ B-split, 384x384 per batch ----------------
__global__ __launch_bounds__(256) void wgemm_mma(int mode) {
    extern __shared__ __align__(16) char sm[];
    const int tid = threadIdx.x, lane = tid & 31, wid = tid >> 5;
    const int wm = wid & 1, wn = wid >> 1;
    const int o0 = (blockIdx.x % 3) * 128;
    const int j0 = (blockIdx.x / 3) * 128;
    const int b = blockIdx.y;
    const int which = blockIdx.z;
    const size_t CC = (size_t)CDIM * CDIM;

    const int widx = mode ? 2 : which;
    const __nv_bfloat16* Ah = g_Whi + (size_t)widx * CC + (size_t)o0 * CDIM;
    const __nv_bfloat16* Al = g_Wlo + (size_t)widx * CC + (size_t)o0 * CDIM;
    const __nv_bfloat16* Bh = (mode ? g_BsThi : g_Ghi) + (size_t)b * CC + (size_t)j0 * CDIM;
    const __nv_bfloat16* Bl = (mode ? g_BsTlo : g_Glo) + (size_t)b * CC + (size_t)j0 * CDIM;

    float acc[4][4][4];
#pragma unroll
    for (int i = 0; i < 4; ++i)
#pragma unroll
        for (int j = 0; j < 4; ++j)
#pragma unroll
            for (int k = 0; k < 4; ++k) acc[i][j][k] = 0.f;

    const uint32_t sb = smem_u32(sm);
    issue_stage(sb, Ah, Al, Bh, Bl, CDIM, CDIM, 0, tid, true);
    CP_COMMIT();

    for (int ch = 0; ch < 12; ++ch) {
        CP_WAIT0();
        __syncthreads();
        if (ch < 11) {
            issue_stage(sb + ((ch + 1) & 1) * STAGE_BYTES, Ah, Al, Bh, Bl,
                        CDIM, CDIM, (ch + 1) * 32, tid, true);
            CP_COMMIT();
        }
        mma_chunk(sb + (ch & 1) * STAGE_BYTES, lane, wm, wn, acc, OFF_BH, OFF_BL);
    }

    if (mode == 0) {
        float* C = (which ? g_Rk : g_Rq) + b * CC;
#pragma unroll
        for (int mi = 0; mi < 4; ++mi)
#pragma unroll
            for (int f = 0; f < 4; ++f) {
                int o = o0 + wm * 64 + mi * 16 + (lane >> 2);
                int j = j0 + wn * 32 + f * 8 + (lane & 3) * 2;
                *(float2*)&C[(size_t)o * CDIM + j] =
                    make_float2(acc[mi][f][0], acc[mi][f][1]);
                *(float2*)&C[(size_t)(o + 8) * CDIM + j] =
                    make_float2(acc[mi][f][2], acc[mi][f][3]);
            }
    } else {
#pragma unroll
        for (int mi = 0; mi < 4; ++mi)
#pragma unroll
            for (int f = 0; f < 4; ++f) {
                int o = o0 + wm * 64 + mi * 16 + (lane >> 2);
                int j = j0 + wn * 32 + f * 8 + (lane & 3) * 2;
#pragma unroll
                for (int half = 0; half < 2; ++half) {
                    float v0 = acc[mi][f][half * 2 + 0];
                    float v1 = acc[mi][f][half * 2 + 1];
                    __nv_bfloat16 h0 = __float2bfloat16(v0);
                    __nv_bfloat16 h1 = __float2bfloat16(v1);
                    __nv_bfloat16 l0 = __float2bfloat16(v0 - __bfloat162float(h0));
                    __nv_bfloat16 l1 = __float2bfloat16(v1 - __bfloat162float(h1));
                    size_t off = b * CC + (size_t)(o + half * 8) * CDIM + j;
                    *(__nv_bfloat162*)(g_Mhi + off) = __nv_bfloat162(h0, h1);
                    *(__nv_bfloat162*)(g_Mlo + off) = __nv_bfloat162(l0, l1);
                }
            }
    }
}

// ---------------- out = M @ x: B read from PLAIN x via ldmatrix.trans ----------------
#define O_BROWB 272
#define O_AH 0
#define O_AL 10240
#define O_BH 20480
#define O_BL (20480 + 32 * O_BROWB)     // 29184
#define O_STAGE (O_BL + 32 * O_BROWB)   // 37888
#define OUT_SMEM (2 * O_STAGE)          // 75776

__global__ __launch_bounds__(256) void out_mma(float* __restrict__ out) {
    extern __shared__ __align__(16) char sm[];
    const int tid = threadIdx.x, lane = tid & 31, wid = tid >> 5;
    const int wm = wid & 1, wn = wid >> 1;
    const int ntile = blockIdx.x;
    const int otile = blockIdx.y;
    const int b = blockIdx.z;
    const size_t CC = (size_t)CDIM * CDIM;

    const __nv_bfloat16* Ah = g_Mhi + (size_t)b * CC + (size_t)(otile * 128) * CDIM;
    const __nv_bfloat16* Al = g_Mlo + (size_t)b * CC + (size_t)(otile * 128) * CDIM;
    const __nv_bfloat16* Xh = g_xhi + (size_t)b * CDIM * HW + (size_t)ntile * 128;
    const __nv_bfloat16* Xl = g_xlo + (size_t)b * CDIM * HW + (size_t)ntile * 128;

    float acc[4][4][4];
#pragma unroll
    for (int i = 0; i < 4; ++i)
#pragma unroll
        for (int j = 0; j < 4; ++j)
#pragma unroll
            for (int k = 0; k < 4; ++k) acc[i][j][k] = 0.f;

    const uint32_t sb = smem_u32(sm);

    auto issue = [&](uint32_t sdst, int cbase) {
#pragma unroll
        for (int t = 0; t < 2; ++t) {
            int idx = t * 256 + tid;
            {   // A: M tile 128o x 32c
                int r = idx >> 2, g = idx & 3;
                uint32_t so = (uint32_t)(r * ROWB + g * 16);
                size_t go = (size_t)r * CDIM + cbase + g * 8;
                cp_async16(sdst + O_AH + so, Ah + go);
                cp_async16(sdst + O_AL + so, Al + go);
            }
            {   // B: x tile 32c x 128n
                int r = idx >> 4, c16 = idx & 15;
                uint32_t so = (uint32_t)(r * O_BROWB + c16 * 16);
                size_t go = (size_t)(cbase + r) * HW + c16 * 8;
                cp_async16(sdst + O_BH + so, Xh + go);
                cp_async16(sdst + O_BL + so, Xl + go);
            }
        }
    };

    issue(sb, 0);
    CP_COMMIT();

    for (int ch = 0; ch < 12; ++ch) {
        CP_WAIT0();
        __syncthreads();
        if (ch < 11) {
            issue(sb + ((ch + 1) & 1) * O_STAGE, (ch + 1) * 32);
            CP_COMMIT();
        }
        const uint32_t sbase = sb + (ch & 1) * O_STAGE;
#pragma unroll
        for (int kk = 0; kk < 2; ++kk) {
            uint32_t a_hi[4][4], a_lo[4][4], b_hi[2][4], b_lo[2][4];
            const uint32_t arow = (uint32_t)(wm * 64 + (lane & 15));
            const uint32_t acol = ((lane >> 4) * 16) + kk * 32;
#pragma unroll
            for (int mi = 0; mi < 4; ++mi) {
                uint32_t off = (arow + mi * 16) * ROWB + acol;
                ldm_x4(a_hi[mi], sbase + O_AH + off);
                ldm_x4(a_lo[mi], sbase + O_AL + off);
            }
            const uint32_t brow = (uint32_t)(kk * 16 + (lane & 7) + ((lane >> 3) & 1) * 8);
#pragma unroll
            for (int nj = 0; nj < 2; ++nj) {
                uint32_t bcol = (uint32_t)(wn * 32 + nj * 16 + (lane >> 4) * 8) * 2;
                uint32_t off = brow * O_BROWB + bcol;
                ldm_x4_trans(b_hi[nj], sbase + O_BH + off);
                ldm_x4_trans(b_lo[nj], sbase + O_BL + off);
            }
#pragma unroll
            for (int t = 0; t < 3; ++t) {
                const uint32_t (*ap)[4] = (t == 2) ? a_lo : a_hi;
                const uint32_t (*bp)[4] = (t == 1) ? b_lo : b_hi;
#pragma unroll
                for (int mi = 0; mi < 4; ++mi)
#pragma unroll
                    for (int nj = 0; nj < 2; ++nj) {
                        mma_bf16(acc[mi][nj * 2 + 0], ap[mi], &bp[nj][0]);
                        mma_bf16(acc[mi][nj * 2 + 1], ap[mi], &bp[nj][2]);
                    }
            }
        }
    }

    const int o0 = otile * 128 + wm * 64;
    const int n0 = ntile * 128 + wn * 32;
#pragma unroll
    for (int mi = 0; mi < 4; ++mi)
#pragma unroll
        for (int f = 0; f < 4; ++f) {
            int o = o0 + mi * 16 + (lane >> 2);
            int n = n0 + f * 8 + (lane & 3) * 2;
            *(float2*)&out[((size_t)b * CDIM + o) * HW + n] =
                make_float2(acc[mi][f][0], acc[mi][f][1]);
            *(float2*)&out[((size_t)b * CDIM + o + 8) * HW + n] =
                make_float2(acc[mi][f][2], acc[mi][f][3]);
        }
}

// ---------------- fp32 SIMT tail ----------------
__global__ void norms_kernel(const float* __restrict__ wq, const float* __restrict__ wk) {
    const int which = blockIdx.x;
    const int b = blockIdx.y;
    const float* R = (which ? g_Rk : g_Rq) + (size_t)b * CDIM * CDIM;
    const float* W = which ? wk : wq;
    float* inv = (which ? g_invk : g_invq) + b * CDIM;
    const int lane = threadIdx.x & 31;
    const int wd = threadIdx.x >> 5;
    for (int r = wd; r < CDIM; r += 12) {
        float s = 0.f;
        for (int j = lane; j < CDIM; j += 32)
            s = fmaf(R[(size_t)r * CDIM + j], W[(size_t)r * CDIM + j], s);
#pragma unroll
        for (int o = 16; o; o >>= 1) s += __shfl_xor_sync(0xffffffffu, s, o);
        if (lane == 0) inv[r] = 1.f / fmaxf(sqrtf(fmaxf(s, 0.f)), EPS);
    }
}

__global__ __launch_bounds__(256) void s_kernel(const float* __restrict__ wk) {
    const int bh = blockIdx.x;
    const int b = bh >> 3;
    const int h = bh & 7;
    const int tid = threadIdx.x;

    __shared__ float qs[CH][68];
    __shared__ float ks[CH][68];

    const int c0 = (tid >> 4) * 3;
    const int d0 = (tid & 15) * 3;

    float acc[3][3];
#pragma unroll
    for (int i = 0; i < 3; ++i)
#pragma unroll
        for (int j = 0; j < 3; ++j) acc[i][j] = 0.f;

    const float* Rq = g_Rq + (size_t)b * CDIM * CDIM + (size_t)(h * CH) * CDIM;
    const float* Wk = wk + (size_t)(h * CH) * CDIM;

    for (int ck = 0; ck < 6; ++ck) {
        const int koff = ck * 64;
#pragma unroll
        for (int t = 0; t < 3; ++t) {
            int idx = t * 256 + tid;
            int row = idx >> 4;
            int col = (idx & 15) * 4;
            *(float4*)&qs[row][col] = *(const float4*)(Rq + (size_t)row * CDIM + koff + col);
            *(float4*)&ks[row][col] = *(const float4*)(Wk + (size_t)row * CDIM + koff + col);
        }
        __syncthreads();
#pragma unroll 8
        for (int kk = 0; kk < 64; ++kk) {
            float q0 = qs[c0 + 0][kk], q1 = qs[c0 + 1][kk], q2 = qs[c0 + 2][kk];
            float k0 = ks[d0 + 0][kk], k1 = ks[d0 + 1][kk], k2 = ks[d0 + 2][kk];
            acc[0][0] = fmaf(q0, k0, acc[0][0]);
            acc[0][1] = fmaf(q0, k1, acc[0][1]);
            acc[0][2] = fmaf(q0, k2, acc[0][2]);
            acc[1][0] = fmaf(q1, k0, acc[1][0]);
            acc[1][1] = fmaf(q1, k1, acc[1][1]);
            acc[1][2] = fmaf(q1, k2, acc[1][2]);
            acc[2][0] = fmaf(q2, k0, acc[2][0]);
            acc[2][1] = fmaf(q2, k1, acc[2][1]);
            acc[2][2] = fmaf(q2, k2, acc[2][2]);
        }
        __syncthreads();
    }

    float* Sb = g_S + (size_t)bh * CH * CH;
#pragma unroll
    for (int i = 0; i < 3; ++i)
#pragma unroll
        for (int j = 0; j < 3; ++j)
            Sb[(c0 + i) * CH + (d0 + j)] = acc[i][j];
}

__global__ void attn_softmax_kernel(const float* __restrict__ temperature) {
    const int bh = blockIdx.x;
    const int b = bh >> 3;
    const int h = bh & 7;
    const int c = threadIdx.x;
    if (c >= CH) return;

    const float t = temperature[h];
    const float sq = g_invq[b * CDIM + h * CH + c] * t;
    const float* Srow = g_S + (size_t)bh * CH * CH + c * CH;
    const float* ik = g_invk + b * CDIM + h * CH;

    float v[CH];
    float m = -1e30f;
#pragma unroll
    for (int d = 0; d < CH; ++d) {
        v[d] = Srow[d] * sq * ik[d];
        m = fmaxf(m, v[d]);
    }
    float sum = 0.f;
#pragma unroll
    for (int d = 0; d < CH; ++d) {
        v[d] = __expf(v[d] - m);
        sum += v[d];
    }
    float inv = 1.f / sum;
    float* Arow = g_A + (size_t)bh * CH * CH + c * CH;
#pragma unroll
    for (int d = 0; d < CH; ++d) Arow[d] = v[d] * inv;
}

__global__ __launch_bounds__(384) void bstack_T(const float* __restrict__ wv) {
    const int bh = blockIdx.x;
    const int b = bh >> 3;
    const int h = bh & 7;

    __shared__ float As[CH * CH];
    const float* Ahp = g_A + (size_t)bh * CH * CH;
    for (int i = threadIdx.x; i < CH * CH; i += 384) As[i] = Ahp[i];
    __syncthreads();

    const int m = threadIdx.x;
    float acc[CH];
#pragma unroll
    for (int i = 0; i < CH; ++i) acc[i] = 0.f;

    const float* wvp = wv + (size_t)(h * CH) * CDIM + m;
    for (int d = 0; d < CH; ++d) {
        float wvv = wvp[(size_t)d * CDIM];
#pragma unroll
        for (int cp = 0; cp < CH; ++cp) acc[cp] = fmaf(As[cp * CH + d], wvv, acc[cp]);
    }
    size_t base = ((size_t)b * CDIM + m) * CDIM + h * CH;
    __align__(16) __nv_bfloat16 hh[CH], ll[CH];
#pragma unroll
    for (int cp = 0; cp < CH; ++cp) {
        __nv_bfloat16 hv = __float2bfloat16(acc[cp]);
        hh[cp] = hv;
        ll[cp] = __float2bfloat16(acc[cp] - __bfloat162float(hv));
    }
#pragma unroll
    for (int q = 0; q < CH / 4; ++q) {
        *(uint2*)(g_BsThi + base + q * 4) = *(const uint2*)(hh + q * 4);
        *(uint2*)(g_BsTlo + base + q * 4) = *(const uint2*)(ll + q * 4);
    }
}

// ---------------- launcher ----------------
extern "C" void kernel_launch(void* const* d_in, const int* in_sizes, int n_in,
                              void* d_out, int out_size) {
    const float* x    = (const float*)d_in[0];
    const float* wq   = (const float*)d_in[1];
    const float* wk   = (const float*)d_in[2];
    const float* wv   = (const float*)d_in[3];
    const float* wo   = (const float*)d_in[4];
    const float* temp = (const float*)d_in[5];
    float* out = (float*)d_out;

    cudaFuncSetAttribute(syrk_mma, cudaFuncAttributeMaxDynamicSharedMemorySize, PIPE_SMEM);
    cudaFuncSetAttribute(wgemm_mma, cudaFuncAttributeMaxDynamicSharedMemorySize, PIPE_SMEM);
    cudaFuncSetAttribute(out_mma, cudaFuncAttributeMaxDynamicSharedMemorySize, OUT_SMEM);

    const size_t CC = (size_t)CDIM * CDIM;
    const int nG = (int)(((size_t)BATCH * CC + 255) / 256);

    convert_plain<<<24576, 256>>>(x);   // also zeroes g_G
    convert_W<<<(CDIM * CDIM + 255) / 256, 256>>>(wq, wk, wo);
    syrk_mma<<<dim3(6, KSPLIT, BATCH), 256, PIPE_SMEM>>>();
    mirror_convert_G<<<nG, 256>>>();

    wgemm_mma<<<dim3(9, BATCH, 2), 256, PIPE_SMEM>>>(0);   // Rq, Rk

    norms_kernel<<<dim3(2, BATCH), 384>>>(wq, wk);
    s_kernel<<<BATCH * NHEAD, 256>>>(wk);
    attn_softmax_kernel<<<BATCH * NHEAD, 64>>>(temp);
    bstack_T<<<BATCH * NHEAD, 384>>>(wv);

    wgemm_mma<<<dim3(9, BATCH, 1), 256, PIPE_SMEM>>>(1);   // Mhi/Mlo

    out_mma<<<dim3(HW / 128, 3, BATCH), 256, OUT_SMEM>>>(out);
}